// round 15
// baseline (speedup 1.0000x reference)
#include <cuda_runtime.h>
#include <cuda_fp16.h>
#include <cstdint>
#include <math.h>

#define BATCH 128
#define CIN   256
#define HCH   256

// ---------------- scratch ----------------
__device__ __half   g_kin [BATCH * 49 * CIN];
__device__ __half   g_sin [BATCH * 961 * CIN];
__device__ __half   g_kbuf[BATCH * HCH * 25];
__device__ __half   g_sbuf[BATCH * HCH * 841];
__device__ __half   g_feat[BATCH * 625 * HCH];
__device__ uint32_t g_awk [294912];
__device__ uint32_t g_aws [294912];
__device__ uint32_t g_awh1[32768];
__device__ uint32_t g_awh2[32768];
__device__ float    g_biask[HCH];
__device__ float    g_biass[HCH];
__device__ float    g_biash[HCH];

// ---------------- helpers ----------------
__device__ __forceinline__ uint32_t smem_u32(const void* p) {
    uint32_t a;
    asm("{ .reg .u64 t; cvta.to.shared.u64 t, %1; cvt.u32.u64 %0, t; }" : "=r"(a) : "l"(p));
    return a;
}
__device__ __forceinline__ void mma_f16(float c[4], const unsigned a[4], const unsigned b[2]) {
    asm volatile(
        "mma.sync.aligned.m16n8k16.row.col.f32.f16.f16.f32 "
        "{%0,%1,%2,%3}, {%4,%5,%6,%7}, {%8,%9}, {%0,%1,%2,%3};"
        : "+f"(c[0]), "+f"(c[1]), "+f"(c[2]), "+f"(c[3])
        : "r"(a[0]), "r"(a[1]), "r"(a[2]), "r"(a[3]), "r"(b[0]), "r"(b[1]));
}

#define CP16(dst, src) \
    asm volatile("cp.async.ca.shared.global [%0], [%1], 16;" :: "r"(dst), "l"(src) : "memory")
#define CP_COMMIT() asm volatile("cp.async.commit_group;" ::: "memory")
#define CP_WAIT(n)  asm volatile("cp.async.wait_group %0;" :: "n"(n) : "memory")

#define LDS128(r0, r1, r2, r3, addr) \
    asm volatile("ld.shared.v4.b32 {%0,%1,%2,%3}, [%4];" \
        : "=r"(r0), "=r"(r1), "=r"(r2), "=r"(r3) : "r"(addr))
#define LDS32(r0, addr) \
    asm volatile("ld.shared.b32 %0, [%1];" : "=r"(r0) : "r"(addr))

// ---------------- prep: NCHW fp32 -> NHWC fp16 (both inputs, one launch) ---
__global__ void nchw2nhwc_all(const float* __restrict__ sIn, __half* __restrict__ sOut,
                              const float* __restrict__ kIn, __half* __restrict__ kOut)
{
    const float* in;
    __half* out;
    int HW, hwTile;
    if (blockIdx.x < 31) { in = sIn; out = sOut; HW = 961; hwTile = blockIdx.x; }
    else                 { in = kIn; out = kOut; HW = 49;  hwTile = blockIdx.x - 31; }

    __shared__ float tile[32][33];
    const int hw0 = hwTile * 32;
    const int c0  = blockIdx.y * 32;
    const int b   = blockIdx.z;
    const int tid = threadIdx.x;

    const int hwl = tid & 31;
    const int cl  = tid >> 5;
#pragma unroll
    for (int pass = 0; pass < 4; pass++) {
        int c = cl + pass * 8;
        int hw = hw0 + hwl;
        tile[c][hwl] = (hw < HW) ? in[((size_t)b * CIN + c0 + c) * HW + hw] : 0.f;
    }
    __syncthreads();

    const int hwo = tid >> 3;
    const int cq  = (tid & 7) * 4;
    if (hw0 + hwo < HW) {
        __half2 h0 = __floats2half2_rn(tile[cq + 0][hwo], tile[cq + 1][hwo]);
        __half2 h1 = __floats2half2_rn(tile[cq + 2][hwo], tile[cq + 3][hwo]);
        __half2* dst = reinterpret_cast<__half2*>(
            out + ((size_t)b * HW + hw0 + hwo) * CIN + c0 + cq);
        dst[0] = h0;
        dst[1] = h1;
    }
}

// ---------------- prep: fold BN + permute weights (fragment order) ----------
__device__ __forceinline__ void permute_one(
    const float* __restrict__ w, const float* __restrict__ gamma,
    const float* __restrict__ beta, const float* __restrict__ mean,
    const float* __restrict__ var, uint32_t* __restrict__ awOut,
    float* __restrict__ biasOut, int K, int KK, int hasBN, int o)
{
    if (o < 256 && hasBN) {
        float inv = rsqrtf(var[o] + 1e-5f) * gamma[o];
        biasOut[o] = beta[o] - mean[o] * inv;
    }
    if (o >= 256 * K / 2) return;

    const int perMb = (K / 32) * 2048;
    int mb = o / perMb;
    int r  = o - mb * perMb;
    int gi = r >> 11;
    int r2 = r & 2047;
    int ks   = r2 >> 10;
    int mi   = (r2 >> 7) & 7;
    int lane = (r2 >> 2) & 31;
    int slot = r2 & 3;

    int row = mb * 128 + mi * 16 + (lane >> 2) + (slot & 1) * 8;
    int k0  = gi * 32 + ks * 16 + (lane & 3) * 2 + ((slot >> 1) & 1) * 8;

    float inv = hasBN ? (rsqrtf(var[row] + 1e-5f) * gamma[row]) : 1.f;

    uint32_t packed = 0;
#pragma unroll
    for (int h = 0; h < 2; h++) {
        int k = k0 + h;
        int col;
        if (KK == 9) { int uv = k >> 8; int ic = k & 255; col = ic * 9 + uv; }
        else col = k;
        float v = w[(size_t)row * K + col] * inv;
        __half hv = __float2half_rn(v);
        packed |= (uint32_t)__half_as_ushort(hv) << (h * 16);
    }
    awOut[o] = packed;
}

__global__ void permute_all(const float* wk, const float* gk, const float* bk,
                            const float* mk, const float* vk, uint32_t* awk, float* biask,
                            const float* ws, const float* gs, const float* bs,
                            const float* ms, const float* vs, uint32_t* aws, float* biass,
                            const float* wh1, const float* gh, const float* bh,
                            const float* mh, const float* vh, uint32_t* awh1, float* biash,
                            const float* wh2, uint32_t* awh2)
{
    int o = blockIdx.x * blockDim.x + threadIdx.x;
    switch (blockIdx.y) {
    case 0: permute_one(wk, gk, bk, mk, vk, awk, biask, 2304, 9, 1, o); break;
    case 1: permute_one(ws, gs, bs, ms, vs, aws, biass, 2304, 9, 1, o); break;
    case 2: permute_one(wh1, gh, bh, mh, vh, awh1, biash, 256, 1, 1, o); break;
    default: permute_one(wh2, nullptr, nullptr, nullptr, nullptr, awh2, nullptr, 256, 1, 0, o);
             break;
    }
}

// ---------------------------------------------------------------------------
// Towers (r9 proven config, frozen).
// ---------------------------------------------------------------------------
#define STAGE 18432
#define SMEM_TOWERS (2 * STAGE)

template<int KS>
__device__ __forceinline__ void
tower_body(const __half* __restrict__ in,
           const uint32_t* __restrict__ aw,
           const float* __restrict__ bias,
           __half* __restrict__ outH,
           int Hin, int Win, int Wout, int PIX, int tileX, int mb)
{
    extern __shared__ char smem[];
    const uint32_t sb = smem_u32(smem);
    const int K = CIN * KS * KS;
    const int NITER = K >> 5;

    const int tid  = threadIdx.x;
    const int lane = tid & 31;
    const int warp = tid >> 5;
    const int wm = warp >> 1, wn = warp & 1;
    const int g = lane >> 2, c = lane & 3;
    const int m0 = mb * 128, n0 = tileX * 128;

    const int bp = tid >> 1;
    const int bh = tid & 1;
    const int gn = n0 + bp;
    const int b  = gn / PIX;
    const int p  = gn - b * PIX;
    const int py = p / Wout;
    const int px = p - py * Wout;
    const __half* inb = in + ((size_t)(b * Hin + py) * Win + px) * 256 + bh * 16;

    const uint32_t* awBlk = aw + (size_t)mb * (K / 32) * 2048;

    auto issue = [&](int gi) {
        const uint32_t stg = sb + (uint32_t)(gi & 1) * STAGE;
        const uint32_t* asrc = awBlk + (size_t)gi * 2048 + tid * 8;
        CP16(stg + tid * 32,      asrc);
        CP16(stg + tid * 32 + 16, asrc + 4);
        int uv = gi >> 3;
        int u = uv / 3, v = uv - u * 3;
        int koff = (u * Win + v) * 256 + (gi & 7) * 32;
        const __half* bsrc = inb + koff;
        uint32_t bd = stg + 8192u + (uint32_t)bp * 80 + bh * 32;
        CP16(bd,      bsrc);
        CP16(bd + 16, bsrc + 8);
        CP_COMMIT();
    };

    float acc[2][8][4];
#pragma unroll
    for (int i = 0; i < 2; i++)
#pragma unroll
        for (int j = 0; j < 8; j++)
#pragma unroll
            for (int e = 0; e < 4; e++) acc[i][j][e] = 0.f;

    issue(0);

    for (int i = 0; i < NITER; i++) {
        CP_WAIT(0);
        __syncthreads();
        if (i + 1 < NITER) issue(i + 1);

        const uint32_t sA = sb + (uint32_t)(i & 1) * STAGE;
        const uint32_t sB = sA + 8192u;
#pragma unroll
        for (int ks = 0; ks < 2; ks++) {
            unsigned afr[2][4], bfr[8][2];
#pragma unroll
            for (int ii = 0; ii < 2; ii++) {
                uint32_t a = sA + (uint32_t)((ks * 8 + wm * 2 + ii) << 9) + lane * 16;
                LDS128(afr[ii][0], afr[ii][1], afr[ii][2], afr[ii][3], a);
            }
#pragma unroll
            for (int j = 0; j < 8; j++) {
                uint32_t a = sB + (uint32_t)(((wn * 8 + j) * 8 + g) * 80 + ks * 32 + c * 4);
                LDS32(bfr[j][0], a);
                LDS32(bfr[j][1], a + 16);
            }
#pragma unroll
            for (int ii = 0; ii < 2; ii++)
#pragma unroll
                for (int j = 0; j < 8; j++)
                    mma_f16(acc[ii][j], afr[ii], bfr[j]);
        }
    }

#pragma unroll
    for (int ii = 0; ii < 2; ii++) {
        int ocA = m0 + wm * 32 + ii * 16 + g;
        int ocB = ocA + 8;
        float biA = bias[ocA];
        float biB = bias[ocB];
#pragma unroll
        for (int j = 0; j < 8; j++) {
            int nb = n0 + wn * 64 + j * 8 + c * 2;
#pragma unroll
            for (int e = 0; e < 4; e++) {
                int nn = nb + (e & 1);
                int oc = (e < 2) ? ocA : ocB;
                float v = fmaxf(acc[ii][j][e] + ((e < 2) ? biA : biB), 0.f);
                int bb = nn / PIX;
                int pp = nn - bb * PIX;
                outH[((size_t)bb * HCH + oc) * PIX + pp] = __float2half_rn(v);
            }
        }
    }
}

__global__ void __launch_bounds__(256, 3)
towers_kernel(const __half* __restrict__ sIn, const uint32_t* __restrict__ sAw,
              const float* __restrict__ sBias, __half* __restrict__ sOut,
              const __half* __restrict__ kIn, const uint32_t* __restrict__ kAw,
              const float* __restrict__ kBias, __half* __restrict__ kOut)
{
    if (blockIdx.x < 841)
        tower_body<3>(sIn, sAw, sBias, sOut, 31, 31, 29, 841, blockIdx.x, blockIdx.y);
    else
        tower_body<3>(kIn, kAw, kBias, kOut, 7, 7, 5, 25, blockIdx.x - 841, blockIdx.y);
}

// ---------------------------------------------------------------------------
// Depthwise xcorr v3: one thread owns one (channel, output-row).
//   - fp32 smem planes (conflict-free: stride 29 words, gcd(29,32)=1)
//   - per u: 29 LDS -> registers, 125 FMA  (145 LDS / 625 FMA per thread)
// Block: 8 channels x 32 lanes (y<25 active) = 256 threads.
// Grid: B x 32 channel-groups = 4096 blocks. smem 27.7 KB.
// Accumulation order per output (u outer, v inner) identical -> bit-exact.
// ---------------------------------------------------------------------------
#define XCH 8
#define XC_SMEM (XCH * 841 * 4 + XCH * 25 * 4)   // 27712 B

__global__ void __launch_bounds__(256)
xcorr_kernel(const __half* __restrict__ s,
             const __half* __restrict__ k,
             __half* __restrict__ feat)
{
    extern __shared__ float xs[];
    float* ss = xs;                  // 8 x 841 fp32
    float* kk = xs + XCH * 841;      // 8 x 25 fp32
    const int cg = blockIdx.x & 31;  // 32 groups of 8 channels
    const int b  = blockIdx.x >> 5;
    const int tid = threadIdx.x;

    // stage planes: fp16 gmem (uint2 = 4 halves) -> fp32 smem
    const uint2* spv = reinterpret_cast<const uint2*>(
        s + ((size_t)b * 256 + cg * XCH) * 841);
    for (int i = tid; i < (XCH * 841) / 4; i += 256) {
        uint2 d = spv[i];
        __half2 h0 = *reinterpret_cast<__half2*>(&d.x);
        __half2 h1 = *reinterpret_cast<__half2*>(&d.y);
        float2 f0 = __half22float2(h0);
        float2 f1 = __half22float2(h1);
        ss[i * 4 + 0] = f0.x; ss[i * 4 + 1] = f0.y;
        ss[i * 4 + 2] = f1.x; ss[i * 4 + 3] = f1.y;
    }
    // stage taps
    const __half* kp = k + ((size_t)b * 256 + cg * XCH) * 25;
    if (tid < XCH * 25) kk[tid] = __half2float(kp[tid]);
    __syncthreads();

    const int y = tid & 31;
    const int c = tid >> 5;          // 0..7
    if (y >= 25) return;

    const float* sc = ss + c * 841;
    const float* kc = kk + c * 25;

    float acc[25];
#pragma unroll
    for (int xo = 0; xo < 25; xo++) acc[xo] = 0.f;

#pragma unroll
    for (int u = 0; u < 5; u++) {
        float r[29];
#pragma unroll
        for (int i = 0; i < 29; i++) r[i] = sc[(y + u) * 29 + i];
        float ku[5];
#pragma unroll
        for (int v = 0; v < 5; v++) ku[v] = kc[u * 5 + v];
#pragma unroll
        for (int xo = 0; xo < 25; xo++)
#pragma unroll
            for (int v = 0; v < 5; v++)
                acc[xo] += r[xo + v] * ku[v];
    }

    // NHWC fp16 stores
    __half* dst = feat + ((size_t)b * 625 + y * 25) * 256 + cg * XCH + c;
#pragma unroll
    for (int xo = 0; xo < 25; xo++)
        dst[xo * 256] = __float2half_rn(acc[xo]);
}

// ---------------------------------------------------------------------------
// Fused head (r13 proven config, frozen).
// ---------------------------------------------------------------------------
#define HF_FB   0
#define HF_H    33792
#define HF_SMEM 67584

__global__ void __launch_bounds__(256, 3)
head_fused(const __half* __restrict__ feat,
           const uint32_t* __restrict__ aw1, const float* __restrict__ bias1,
           const uint32_t* __restrict__ aw2, const float* __restrict__ bias2,
           float* __restrict__ out)
{
    extern __shared__ char smem[];
    const uint32_t sb = smem_u32(smem);
    __half* hsm = reinterpret_cast<__half*>(smem + HF_H);

    const int tid  = threadIdx.x;
    const int lane = tid & 31;
    const int warp = tid >> 5;
    const int wm = warp >> 1, wn = warp & 1;
    const int g = lane >> 2, c = lane & 3;
    const int n0 = blockIdx.x * 64;

    {
        const int px = tid >> 2;
        const int q  = tid & 3;
        const __half* src = feat + (size_t)(n0 + px) * 256 + q * 64;
        uint32_t dst = sb + HF_FB + (uint32_t)px * 528 + q * 128;
#pragma unroll
        for (int t = 0; t < 8; t++) CP16(dst + t * 16, src + t * 8);
        CP_COMMIT();
        CP_WAIT(0);
    }
    __syncthreads();

    float acc[2][4][4];

    // ---- stage 1 ----
#pragma unroll 1
    for (int mb = 0; mb < 2; mb++) {
        const uint4* awq = reinterpret_cast<const uint4*>(aw1 + (size_t)mb * 8 * 2048);
#pragma unroll
        for (int i = 0; i < 2; i++)
#pragma unroll
            for (int j = 0; j < 4; j++)
#pragma unroll
                for (int e = 0; e < 4; e++) acc[i][j][e] = 0.f;

#pragma unroll 2
        for (int i = 0; i < 8; i++) {
#pragma unroll
            for (int ks = 0; ks < 2; ks++) {
                unsigned afr[2][4], bfr[4][2];
#pragma unroll
                for (int ii = 0; ii < 2; ii++) {
                    uint4 v4 = awq[(size_t)i * 512 + (ks * 8 + wm * 2 + ii) * 32 + lane];
                    afr[ii][0] = v4.x; afr[ii][1] = v4.y;
                    afr[ii][2] = v4.z; afr[ii][3] = v4.w;
                }
#pragma unroll
                for (int j = 0; j < 4; j++) {
                    uint32_t a = sb + HF_FB
                               + (uint32_t)(((wn * 4 + j) * 8 + g) * 528
                                            + i * 64 + ks * 32 + c * 4);
                    LDS32(bfr[j][0], a);
                    LDS32(bfr[j][1], a + 16);
                }
#pragma unroll
                for (int ii = 0; ii < 2; ii++)
#pragma unroll
                    for (int j = 0; j < 4; j++)
                        mma_f16(acc[ii][j], afr[ii], bfr[j]);
            }
        }

#pragma unroll
        for (int ii = 0; ii < 2; ii++) {
            int oclA = mb * 128 + wm * 32 + ii * 16 + g;
            float biA = bias1[oclA];
            float biB = bias1[oclA + 8];
#pragma unroll
            for (int j = 0; j < 4; j++) {
                int nl = wn * 32 + j * 8 + c * 2;
#pragma unroll
                for (int e = 0; e < 4; e++) {
                    int n = nl + (e & 1);
                    int ocl = oclA + ((e < 2) ? 0 : 8);
                    float v = fmaxf(acc[ii][j][e] + ((e < 2) ? biA : biB), 0.f);
                    hsm[n * 264 + ocl] = __float2half_rn(v);
                }
            }
        }
    }
    __syncthreads();

    // ---- stage 2 (barrier-free) ----
#pragma unroll 1
    for (int mb2 = 0; mb2 < 2; mb2++) {
        const uint4* awq = reinterpret_cast<const uint4*>(aw2 + (size_t)mb2 * 8 * 2048);
#pragma unroll
        for (int i = 0; i < 2; i++)
#pragma unroll
            for (int j = 0; j < 4; j++)
#pragma unroll
                for (int e = 0; e < 4; e++) acc[i][j][e] = 0.f;

        const uint32_t hB = sb + HF_H;
#pragma unroll 2
        for (int i = 0; i < 8; i++) {
#pragma unroll
            for (int ks = 0; ks < 2; ks++) {
                unsigned afr[2][4], bfr[4][2];
#pragma unroll
                for (int ii = 0; ii < 2; ii++) {
                    uint4 v4 = awq[(size_t)i * 512 + (ks * 8 + wm * 2 + ii) * 32 + lane];
                    afr[ii][0] = v4.x; afr[ii][1] = v4.y;
                    afr[ii][2] = v4.z; afr[ii][3] = v4.w;
                }
#pragma unroll
                for (int j = 0; j < 4; j++) {
                    uint32_t a = hB + (uint32_t)(((wn * 4 + j) * 8 + g) * 528
                                                 + i * 64 + ks * 32 + c * 4);
                    LDS32(bfr[j][0], a);
                    LDS32(bfr[j][1], a + 16);
                }
#pragma unroll
                for (int ii = 0; ii < 2; ii++)
#pragma unroll
                    for (int j = 0; j < 4; j++)
                        mma_f16(acc[ii][j], afr[ii], bfr[j]);
            }
        }

#pragma unroll
        for (int ii = 0; ii < 2; ii++) {
            int ocA = mb2 * 128 + wm * 32 + ii * 16 + g;
            int ocB = ocA + 8;
            float biA = bias2[ocA];
            float biB = bias2[ocB];
#pragma unroll
            for (int j = 0; j < 4; j++) {
                int nb = n0 + wn * 32 + j * 8 + c * 2;
#pragma unroll
                for (int e = 0; e < 4; e++) {
                    int nn = nb + (e & 1);
                    int oc = (e < 2) ? ocA : ocB;
                    float v = acc[ii][j][e] + ((e < 2) ? biA : biB);
                    int bb = nn / 625;
                    int pp = nn - bb * 625;
                    out[((size_t)bb * HCH + oc) * 625 + pp] = v;
                }
            }
        }
    }
}

// ---------------------------------------------------------------------------
extern "C" void kernel_launch(void* const* d_in, const int* in_sizes, int n_in,
                              void* d_out, int out_size)
{
    (void)in_sizes; (void)n_in; (void)out_size;
    const float* in_kernel = (const float*)d_in[0];
    const float* in_search = (const float*)d_in[1];
    const float* wk = (const float*)d_in[2];
    const float* gk = (const float*)d_in[3];
    const float* bk = (const float*)d_in[4];
    const float* mk = (const float*)d_in[5];
    const float* vk = (const float*)d_in[6];
    const float* ws = (const float*)d_in[7];
    const float* gs = (const float*)d_in[8];
    const float* bs = (const float*)d_in[9];
    const float* ms = (const float*)d_in[10];
    const float* vs = (const float*)d_in[11];
    const float* wh1 = (const float*)d_in[12];
    const float* gh  = (const float*)d_in[13];
    const float* bh  = (const float*)d_in[14];
    const float* mh  = (const float*)d_in[15];
    const float* vh  = (const float*)d_in[16];
    const float* wh2 = (const float*)d_in[17];
    const float* bh2 = (const float*)d_in[18];
    float* out = (float*)d_out;

    __half *kin, *sin_, *kbuf, *sbuf, *feat;
    float *biask, *biass, *biash;
    uint32_t *awk, *aws, *awh1, *awh2;
    cudaGetSymbolAddress((void**)&kin,   g_kin);
    cudaGetSymbolAddress((void**)&sin_,  g_sin);
    cudaGetSymbolAddress((void**)&kbuf,  g_kbuf);
    cudaGetSymbolAddress((void**)&sbuf,  g_sbuf);
    cudaGetSymbolAddress((void**)&feat,  g_feat);
    cudaGetSymbolAddress((void**)&awk,   g_awk);
    cudaGetSymbolAddress((void**)&aws,   g_aws);
    cudaGetSymbolAddress((void**)&awh1,  g_awh1);
    cudaGetSymbolAddress((void**)&awh2,  g_awh2);
    cudaGetSymbolAddress((void**)&biask, g_biask);
    cudaGetSymbolAddress((void**)&biass, g_biass);
    cudaGetSymbolAddress((void**)&biash, g_biash);

    cudaFuncSetAttribute(towers_kernel,
                         cudaFuncAttributeMaxDynamicSharedMemorySize, SMEM_TOWERS);
    cudaFuncSetAttribute(head_fused,
                         cudaFuncAttributeMaxDynamicSharedMemorySize, HF_SMEM);
    cudaFuncSetAttribute(xcorr_kernel,
                         cudaFuncAttributeMaxDynamicSharedMemorySize, XC_SMEM);

    // #1: both layout conversions
    nchw2nhwc_all<<<dim3(33, 8, BATCH), 256>>>(in_search, sin_, in_kernel, kin);

    // #2: weight permutes
    permute_all<<<dim3(1152, 4), 256>>>(wk, gk, bk, mk, vk, awk, biask,
                                        ws, gs, bs, ms, vs, aws, biass,
                                        wh1, gh, bh, mh, vh, awh1, biash,
                                        wh2, awh2);

    // #3: towers (frozen)
    towers_kernel<<<dim3(866, 2), 256, SMEM_TOWERS>>>(
        sin_, aws, biass, sbuf, kin, awk, biask, kbuf);

    // #4: xcorr v3 (ncu capture target)
    xcorr_kernel<<<BATCH * 32, 256, XC_SMEM>>>(sbuf, kbuf, feat);

    // #5: fused head (frozen)
    head_fused<<<1250, 256, HF_SMEM>>>(feat, awh1, biash, awh2, bh2, out);
}

// round 16
// speedup vs baseline: 1.1504x; 1.1504x over previous
#include <cuda_runtime.h>
#include <cuda_fp16.h>
#include <cstdint>
#include <math.h>

#define BATCH 128
#define CIN   256
#define HCH   256

// ---------------- scratch ----------------
__device__ __half   g_kin [BATCH * 49 * CIN];
__device__ __half   g_sin [BATCH * 961 * CIN];
__device__ __half   g_kbuf[BATCH * HCH * 25];
__device__ __half   g_sbuf[BATCH * HCH * 841];
__device__ __half   g_feat[BATCH * 625 * HCH];
__device__ uint32_t g_awk [294912];
__device__ uint32_t g_aws [294912];
__device__ uint32_t g_awh1[32768];
__device__ uint32_t g_awh2[32768];
__device__ float    g_biask[HCH];
__device__ float    g_biass[HCH];
__device__ float    g_biash[HCH];

// ---------------- helpers ----------------
__device__ __forceinline__ uint32_t smem_u32(const void* p) {
    uint32_t a;
    asm("{ .reg .u64 t; cvta.to.shared.u64 t, %1; cvt.u32.u64 %0, t; }" : "=r"(a) : "l"(p));
    return a;
}
__device__ __forceinline__ void mma_f16(float c[4], const unsigned a[4], const unsigned b[2]) {
    asm volatile(
        "mma.sync.aligned.m16n8k16.row.col.f32.f16.f16.f32 "
        "{%0,%1,%2,%3}, {%4,%5,%6,%7}, {%8,%9}, {%0,%1,%2,%3};"
        : "+f"(c[0]), "+f"(c[1]), "+f"(c[2]), "+f"(c[3])
        : "r"(a[0]), "r"(a[1]), "r"(a[2]), "r"(a[3]), "r"(b[0]), "r"(b[1]));
}

#define CP16(dst, src) \
    asm volatile("cp.async.ca.shared.global [%0], [%1], 16;" :: "r"(dst), "l"(src) : "memory")
#define CP_COMMIT() asm volatile("cp.async.commit_group;" ::: "memory")
#define CP_WAIT(n)  asm volatile("cp.async.wait_group %0;" :: "n"(n) : "memory")

#define LDS128(r0, r1, r2, r3, addr) \
    asm volatile("ld.shared.v4.b32 {%0,%1,%2,%3}, [%4];" \
        : "=r"(r0), "=r"(r1), "=r"(r2), "=r"(r3) : "r"(addr))
#define LDS32(r0, addr) \
    asm volatile("ld.shared.b32 %0, [%1];" : "=r"(r0) : "r"(addr))

// ---------------- prep: NCHW fp32 -> NHWC fp16 (both inputs, one launch) ---
__global__ void nchw2nhwc_all(const float* __restrict__ sIn, __half* __restrict__ sOut,
                              const float* __restrict__ kIn, __half* __restrict__ kOut)
{
    const float* in;
    __half* out;
    int HW, hwTile;
    if (blockIdx.x < 31) { in = sIn; out = sOut; HW = 961; hwTile = blockIdx.x; }
    else                 { in = kIn; out = kOut; HW = 49;  hwTile = blockIdx.x - 31; }

    __shared__ float tile[32][33];
    const int hw0 = hwTile * 32;
    const int c0  = blockIdx.y * 32;
    const int b   = blockIdx.z;
    const int tid = threadIdx.x;

    const int hwl = tid & 31;
    const int cl  = tid >> 5;
#pragma unroll
    for (int pass = 0; pass < 4; pass++) {
        int c = cl + pass * 8;
        int hw = hw0 + hwl;
        tile[c][hwl] = (hw < HW) ? in[((size_t)b * CIN + c0 + c) * HW + hw] : 0.f;
    }
    __syncthreads();

    const int hwo = tid >> 3;
    const int cq  = (tid & 7) * 4;
    if (hw0 + hwo < HW) {
        __half2 h0 = __floats2half2_rn(tile[cq + 0][hwo], tile[cq + 1][hwo]);
        __half2 h1 = __floats2half2_rn(tile[cq + 2][hwo], tile[cq + 3][hwo]);
        __half2* dst = reinterpret_cast<__half2*>(
            out + ((size_t)b * HW + hw0 + hwo) * CIN + c0 + cq);
        dst[0] = h0;
        dst[1] = h1;
    }
}

// ---------------- prep: fold BN + permute weights (fragment order) ----------
__device__ __forceinline__ void permute_one(
    const float* __restrict__ w, const float* __restrict__ gamma,
    const float* __restrict__ beta, const float* __restrict__ mean,
    const float* __restrict__ var, uint32_t* __restrict__ awOut,
    float* __restrict__ biasOut, int K, int KK, int hasBN, int o)
{
    if (o < 256 && hasBN) {
        float inv = rsqrtf(var[o] + 1e-5f) * gamma[o];
        biasOut[o] = beta[o] - mean[o] * inv;
    }
    if (o >= 256 * K / 2) return;

    const int perMb = (K / 32) * 2048;
    int mb = o / perMb;
    int r  = o - mb * perMb;
    int gi = r >> 11;
    int r2 = r & 2047;
    int ks   = r2 >> 10;
    int mi   = (r2 >> 7) & 7;
    int lane = (r2 >> 2) & 31;
    int slot = r2 & 3;

    int row = mb * 128 + mi * 16 + (lane >> 2) + (slot & 1) * 8;
    int k0  = gi * 32 + ks * 16 + (lane & 3) * 2 + ((slot >> 1) & 1) * 8;

    float inv = hasBN ? (rsqrtf(var[row] + 1e-5f) * gamma[row]) : 1.f;

    uint32_t packed = 0;
#pragma unroll
    for (int h = 0; h < 2; h++) {
        int k = k0 + h;
        int col;
        if (KK == 9) { int uv = k >> 8; int ic = k & 255; col = ic * 9 + uv; }
        else col = k;
        float v = w[(size_t)row * K + col] * inv;
        __half hv = __float2half_rn(v);
        packed |= (uint32_t)__half_as_ushort(hv) << (h * 16);
    }
    awOut[o] = packed;
}

__global__ void permute_all(const float* wk, const float* gk, const float* bk,
                            const float* mk, const float* vk, uint32_t* awk, float* biask,
                            const float* ws, const float* gs, const float* bs,
                            const float* ms, const float* vs, uint32_t* aws, float* biass,
                            const float* wh1, const float* gh, const float* bh,
                            const float* mh, const float* vh, uint32_t* awh1, float* biash,
                            const float* wh2, uint32_t* awh2)
{
    int o = blockIdx.x * blockDim.x + threadIdx.x;
    switch (blockIdx.y) {
    case 0: permute_one(wk, gk, bk, mk, vk, awk, biask, 2304, 9, 1, o); break;
    case 1: permute_one(ws, gs, bs, ms, vs, aws, biass, 2304, 9, 1, o); break;
    case 2: permute_one(wh1, gh, bh, mh, vh, awh1, biash, 256, 1, 1, o); break;
    default: permute_one(wh2, nullptr, nullptr, nullptr, nullptr, awh2, nullptr, 256, 1, 0, o);
             break;
    }
}

// ---------------------------------------------------------------------------
// Towers (r9 proven config, frozen).
// ---------------------------------------------------------------------------
#define STAGE 18432
#define SMEM_TOWERS (2 * STAGE)

template<int KS>
__device__ __forceinline__ void
tower_body(const __half* __restrict__ in,
           const uint32_t* __restrict__ aw,
           const float* __restrict__ bias,
           __half* __restrict__ outH,
           int Hin, int Win, int Wout, int PIX, int tileX, int mb)
{
    extern __shared__ char smem[];
    const uint32_t sb = smem_u32(smem);
    const int K = CIN * KS * KS;
    const int NITER = K >> 5;

    const int tid  = threadIdx.x;
    const int lane = tid & 31;
    const int warp = tid >> 5;
    const int wm = warp >> 1, wn = warp & 1;
    const int g = lane >> 2, c = lane & 3;
    const int m0 = mb * 128, n0 = tileX * 128;

    const int bp = tid >> 1;
    const int bh = tid & 1;
    const int gn = n0 + bp;
    const int b  = gn / PIX;
    const int p  = gn - b * PIX;
    const int py = p / Wout;
    const int px = p - py * Wout;
    const __half* inb = in + ((size_t)(b * Hin + py) * Win + px) * 256 + bh * 16;

    const uint32_t* awBlk = aw + (size_t)mb * (K / 32) * 2048;

    auto issue = [&](int gi) {
        const uint32_t stg = sb + (uint32_t)(gi & 1) * STAGE;
        const uint32_t* asrc = awBlk + (size_t)gi * 2048 + tid * 8;
        CP16(stg + tid * 32,      asrc);
        CP16(stg + tid * 32 + 16, asrc + 4);
        int uv = gi >> 3;
        int u = uv / 3, v = uv - u * 3;
        int koff = (u * Win + v) * 256 + (gi & 7) * 32;
        const __half* bsrc = inb + koff;
        uint32_t bd = stg + 8192u + (uint32_t)bp * 80 + bh * 32;
        CP16(bd,      bsrc);
        CP16(bd + 16, bsrc + 8);
        CP_COMMIT();
    };

    float acc[2][8][4];
#pragma unroll
    for (int i = 0; i < 2; i++)
#pragma unroll
        for (int j = 0; j < 8; j++)
#pragma unroll
            for (int e = 0; e < 4; e++) acc[i][j][e] = 0.f;

    issue(0);

    for (int i = 0; i < NITER; i++) {
        CP_WAIT(0);
        __syncthreads();
        if (i + 1 < NITER) issue(i + 1);

        const uint32_t sA = sb + (uint32_t)(i & 1) * STAGE;
        const uint32_t sB = sA + 8192u;
#pragma unroll
        for (int ks = 0; ks < 2; ks++) {
            unsigned afr[2][4], bfr[8][2];
#pragma unroll
            for (int ii = 0; ii < 2; ii++) {
                uint32_t a = sA + (uint32_t)((ks * 8 + wm * 2 + ii) << 9) + lane * 16;
                LDS128(afr[ii][0], afr[ii][1], afr[ii][2], afr[ii][3], a);
            }
#pragma unroll
            for (int j = 0; j < 8; j++) {
                uint32_t a = sB + (uint32_t)(((wn * 8 + j) * 8 + g) * 80 + ks * 32 + c * 4);
                LDS32(bfr[j][0], a);
                LDS32(bfr[j][1], a + 16);
            }
#pragma unroll
            for (int ii = 0; ii < 2; ii++)
#pragma unroll
                for (int j = 0; j < 8; j++)
                    mma_f16(acc[ii][j], afr[ii], bfr[j]);
        }
    }

#pragma unroll
    for (int ii = 0; ii < 2; ii++) {
        int ocA = m0 + wm * 32 + ii * 16 + g;
        int ocB = ocA + 8;
        float biA = bias[ocA];
        float biB = bias[ocB];
#pragma unroll
        for (int j = 0; j < 8; j++) {
            int nb = n0 + wn * 64 + j * 8 + c * 2;
#pragma unroll
            for (int e = 0; e < 4; e++) {
                int nn = nb + (e & 1);
                int oc = (e < 2) ? ocA : ocB;
                float v = fmaxf(acc[ii][j][e] + ((e < 2) ? biA : biB), 0.f);
                int bb = nn / PIX;
                int pp = nn - bb * PIX;
                outH[((size_t)bb * HCH + oc) * PIX + pp] = __float2half_rn(v);
            }
        }
    }
}

__global__ void __launch_bounds__(256, 3)
towers_kernel(const __half* __restrict__ sIn, const uint32_t* __restrict__ sAw,
              const float* __restrict__ sBias, __half* __restrict__ sOut,
              const __half* __restrict__ kIn, const uint32_t* __restrict__ kAw,
              const float* __restrict__ kBias, __half* __restrict__ kOut)
{
    if (blockIdx.x < 841)
        tower_body<3>(sIn, sAw, sBias, sOut, 31, 31, 29, 841, blockIdx.x, blockIdx.y);
    else
        tower_body<3>(kIn, kAw, kBias, kOut, 7, 7, 5, 25, blockIdx.x - 841, blockIdx.y);
}

// ---------------------------------------------------------------------------
// Depthwise xcorr v4: v3 register-row-reuse compute + smem-staged coalesced
// stores. Block = 512 threads (16 ch x 32 y-slots, y<25 active).
//   compute: per u: 29 LDS -> regs, 125 FMA  (145 LDS / 625 FMA / thread)
//   output:  staged to smem fp16 [625][16], then 32B-sector gmem stores
// smem: planes 16*841*4 + taps 16*25*4 + out 625*16*2 = 75424 B -> 2 CTA/SM.
// Accumulation order (u outer, v inner) unchanged -> bit-exact.
// ---------------------------------------------------------------------------
#define XC_SMEM (16 * 841 * 4 + 16 * 25 * 4 + 625 * 16 * 2)   // 75424

__global__ void __launch_bounds__(512)
xcorr_kernel(const __half* __restrict__ s,
             const __half* __restrict__ k,
             __half* __restrict__ feat)
{
    extern __shared__ float xs[];
    float*  ss = xs;                       // 16 x 841 fp32
    float*  kk = xs + 16 * 841;            // 16 x 25 fp32
    __half* ob = reinterpret_cast<__half*>(kk + 16 * 25);   // [625][16] fp16
    const int cg = blockIdx.x & 15;
    const int b  = blockIdx.x >> 4;
    const int tid = threadIdx.x;

    // stage planes: fp16 gmem (uint2 = 4 halves) -> fp32 smem, coalesced
    const uint2* spv = reinterpret_cast<const uint2*>(
        s + ((size_t)b * 256 + cg * 16) * 841);
    for (int i = tid; i < (16 * 841) / 4; i += 512) {
        uint2 d = spv[i];
        __half2 h0 = *reinterpret_cast<__half2*>(&d.x);
        __half2 h1 = *reinterpret_cast<__half2*>(&d.y);
        float2 f0 = __half22float2(h0);
        float2 f1 = __half22float2(h1);
        ss[i * 4 + 0] = f0.x; ss[i * 4 + 1] = f0.y;
        ss[i * 4 + 2] = f1.x; ss[i * 4 + 3] = f1.y;
    }
    const __half* kp = k + ((size_t)b * 256 + cg * 16) * 25;
    if (tid < 16 * 25) kk[tid] = __half2float(kp[tid]);
    __syncthreads();

    const int c = tid & 15;
    const int y = tid >> 4;          // 0..31
    if (y < 25) {
        const float* sc = ss + c * 841;
        const float* kc = kk + c * 25;

        float acc[25];
#pragma unroll
        for (int xo = 0; xo < 25; xo++) acc[xo] = 0.f;

#pragma unroll
        for (int u = 0; u < 5; u++) {
            float r[29];
#pragma unroll
            for (int i = 0; i < 29; i++) r[i] = sc[(y + u) * 29 + i];
            float ku[5];
#pragma unroll
            for (int v = 0; v < 5; v++) ku[v] = kc[u * 5 + v];
#pragma unroll
            for (int xo = 0; xo < 25; xo++)
#pragma unroll
                for (int v = 0; v < 5; v++)
                    acc[xo] += r[xo + v] * ku[v];
        }

        // stage outputs in smem (lane-contiguous in c)
#pragma unroll
        for (int xo = 0; xo < 25; xo++)
            ob[(y * 25 + xo) * 16 + c] = __float2half_rn(acc[xo]);
    }
    __syncthreads();

    // coalesced store pass: per pixel 16 ch = 32 B = one full sector
    const uint4* obv = reinterpret_cast<const uint4*>(ob);
    uint4* dstv = reinterpret_cast<uint4*>(feat);
    const size_t base = (size_t)b * 625 * 32 + cg * 2;   // uint4 units
    for (int p = tid; p < 625; p += 512) {
        dstv[base + (size_t)p * 32 + 0] = obv[p * 2 + 0];
        dstv[base + (size_t)p * 32 + 1] = obv[p * 2 + 1];
    }
}

// ---------------------------------------------------------------------------
// Fused head (r13 proven config, frozen).
// ---------------------------------------------------------------------------
#define HF_FB   0
#define HF_H    33792
#define HF_SMEM 67584

__global__ void __launch_bounds__(256, 3)
head_fused(const __half* __restrict__ feat,
           const uint32_t* __restrict__ aw1, const float* __restrict__ bias1,
           const uint32_t* __restrict__ aw2, const float* __restrict__ bias2,
           float* __restrict__ out)
{
    extern __shared__ char smem[];
    const uint32_t sb = smem_u32(smem);
    __half* hsm = reinterpret_cast<__half*>(smem + HF_H);

    const int tid  = threadIdx.x;
    const int lane = tid & 31;
    const int warp = tid >> 5;
    const int wm = warp >> 1, wn = warp & 1;
    const int g = lane >> 2, c = lane & 3;
    const int n0 = blockIdx.x * 64;

    {
        const int px = tid >> 2;
        const int q  = tid & 3;
        const __half* src = feat + (size_t)(n0 + px) * 256 + q * 64;
        uint32_t dst = sb + HF_FB + (uint32_t)px * 528 + q * 128;
#pragma unroll
        for (int t = 0; t < 8; t++) CP16(dst + t * 16, src + t * 8);
        CP_COMMIT();
        CP_WAIT(0);
    }
    __syncthreads();

    float acc[2][4][4];

    // ---- stage 1 ----
#pragma unroll 1
    for (int mb = 0; mb < 2; mb++) {
        const uint4* awq = reinterpret_cast<const uint4*>(aw1 + (size_t)mb * 8 * 2048);
#pragma unroll
        for (int i = 0; i < 2; i++)
#pragma unroll
            for (int j = 0; j < 4; j++)
#pragma unroll
                for (int e = 0; e < 4; e++) acc[i][j][e] = 0.f;

#pragma unroll 2
        for (int i = 0; i < 8; i++) {
#pragma unroll
            for (int ks = 0; ks < 2; ks++) {
                unsigned afr[2][4], bfr[4][2];
#pragma unroll
                for (int ii = 0; ii < 2; ii++) {
                    uint4 v4 = awq[(size_t)i * 512 + (ks * 8 + wm * 2 + ii) * 32 + lane];
                    afr[ii][0] = v4.x; afr[ii][1] = v4.y;
                    afr[ii][2] = v4.z; afr[ii][3] = v4.w;
                }
#pragma unroll
                for (int j = 0; j < 4; j++) {
                    uint32_t a = sb + HF_FB
                               + (uint32_t)(((wn * 4 + j) * 8 + g) * 528
                                            + i * 64 + ks * 32 + c * 4);
                    LDS32(bfr[j][0], a);
                    LDS32(bfr[j][1], a + 16);
                }
#pragma unroll
                for (int ii = 0; ii < 2; ii++)
#pragma unroll
                    for (int j = 0; j < 4; j++)
                        mma_f16(acc[ii][j], afr[ii], bfr[j]);
            }
        }

#pragma unroll
        for (int ii = 0; ii < 2; ii++) {
            int oclA = mb * 128 + wm * 32 + ii * 16 + g;
            float biA = bias1[oclA];
            float biB = bias1[oclA + 8];
#pragma unroll
            for (int j = 0; j < 4; j++) {
                int nl = wn * 32 + j * 8 + c * 2;
#pragma unroll
                for (int e = 0; e < 4; e++) {
                    int n = nl + (e & 1);
                    int ocl = oclA + ((e < 2) ? 0 : 8);
                    float v = fmaxf(acc[ii][j][e] + ((e < 2) ? biA : biB), 0.f);
                    hsm[n * 264 + ocl] = __float2half_rn(v);
                }
            }
        }
    }
    __syncthreads();

    // ---- stage 2 (barrier-free) ----
#pragma unroll 1
    for (int mb2 = 0; mb2 < 2; mb2++) {
        const uint4* awq = reinterpret_cast<const uint4*>(aw2 + (size_t)mb2 * 8 * 2048);
#pragma unroll
        for (int i = 0; i < 2; i++)
#pragma unroll
            for (int j = 0; j < 4; j++)
#pragma unroll
                for (int e = 0; e < 4; e++) acc[i][j][e] = 0.f;

        const uint32_t hB = sb + HF_H;
#pragma unroll 2
        for (int i = 0; i < 8; i++) {
#pragma unroll
            for (int ks = 0; ks < 2; ks++) {
                unsigned afr[2][4], bfr[4][2];
#pragma unroll
                for (int ii = 0; ii < 2; ii++) {
                    uint4 v4 = awq[(size_t)i * 512 + (ks * 8 + wm * 2 + ii) * 32 + lane];
                    afr[ii][0] = v4.x; afr[ii][1] = v4.y;
                    afr[ii][2] = v4.z; afr[ii][3] = v4.w;
                }
#pragma unroll
                for (int j = 0; j < 4; j++) {
                    uint32_t a = hB + (uint32_t)(((wn * 4 + j) * 8 + g) * 528
                                                 + i * 64 + ks * 32 + c * 4);
                    LDS32(bfr[j][0], a);
                    LDS32(bfr[j][1], a + 16);
                }
#pragma unroll
                for (int ii = 0; ii < 2; ii++)
#pragma unroll
                    for (int j = 0; j < 4; j++)
                        mma_f16(acc[ii][j], afr[ii], bfr[j]);
            }
        }

#pragma unroll
        for (int ii = 0; ii < 2; ii++) {
            int ocA = mb2 * 128 + wm * 32 + ii * 16 + g;
            int ocB = ocA + 8;
            float biA = bias2[ocA];
            float biB = bias2[ocB];
#pragma unroll
            for (int j = 0; j < 4; j++) {
                int nb = n0 + wn * 32 + j * 8 + c * 2;
#pragma unroll
                for (int e = 0; e < 4; e++) {
                    int nn = nb + (e & 1);
                    int oc = (e < 2) ? ocA : ocB;
                    float v = acc[ii][j][e] + ((e < 2) ? biA : biB);
                    int bb = nn / 625;
                    int pp = nn - bb * 625;
                    out[((size_t)bb * HCH + oc) * 625 + pp] = v;
                }
            }
        }
    }
}

// ---------------------------------------------------------------------------
extern "C" void kernel_launch(void* const* d_in, const int* in_sizes, int n_in,
                              void* d_out, int out_size)
{
    (void)in_sizes; (void)n_in; (void)out_size;
    const float* in_kernel = (const float*)d_in[0];
    const float* in_search = (const float*)d_in[1];
    const float* wk = (const float*)d_in[2];
    const float* gk = (const float*)d_in[3];
    const float* bk = (const float*)d_in[4];
    const float* mk = (const float*)d_in[5];
    const float* vk = (const float*)d_in[6];
    const float* ws = (const float*)d_in[7];
    const float* gs = (const float*)d_in[8];
    const float* bs = (const float*)d_in[9];
    const float* ms = (const float*)d_in[10];
    const float* vs = (const float*)d_in[11];
    const float* wh1 = (const float*)d_in[12];
    const float* gh  = (const float*)d_in[13];
    const float* bh  = (const float*)d_in[14];
    const float* mh  = (const float*)d_in[15];
    const float* vh  = (const float*)d_in[16];
    const float* wh2 = (const float*)d_in[17];
    const float* bh2 = (const float*)d_in[18];
    float* out = (float*)d_out;

    __half *kin, *sin_, *kbuf, *sbuf, *feat;
    float *biask, *biass, *biash;
    uint32_t *awk, *aws, *awh1, *awh2;
    cudaGetSymbolAddress((void**)&kin,   g_kin);
    cudaGetSymbolAddress((void**)&sin_,  g_sin);
    cudaGetSymbolAddress((void**)&kbuf,  g_kbuf);
    cudaGetSymbolAddress((void**)&sbuf,  g_sbuf);
    cudaGetSymbolAddress((void**)&feat,  g_feat);
    cudaGetSymbolAddress((void**)&awk,   g_awk);
    cudaGetSymbolAddress((void**)&aws,   g_aws);
    cudaGetSymbolAddress((void**)&awh1,  g_awh1);
    cudaGetSymbolAddress((void**)&awh2,  g_awh2);
    cudaGetSymbolAddress((void**)&biask, g_biask);
    cudaGetSymbolAddress((void**)&biass, g_biass);
    cudaGetSymbolAddress((void**)&biash, g_biash);

    cudaFuncSetAttribute(towers_kernel,
                         cudaFuncAttributeMaxDynamicSharedMemorySize, SMEM_TOWERS);
    cudaFuncSetAttribute(head_fused,
                         cudaFuncAttributeMaxDynamicSharedMemorySize, HF_SMEM);
    cudaFuncSetAttribute(xcorr_kernel,
                         cudaFuncAttributeMaxDynamicSharedMemorySize, XC_SMEM);

    // #1: both layout conversions
    nchw2nhwc_all<<<dim3(33, 8, BATCH), 256>>>(in_search, sin_, in_kernel, kin);

    // #2: weight permutes
    permute_all<<<dim3(1152, 4), 256>>>(wk, gk, bk, mk, vk, awk, biask,
                                        ws, gs, bs, ms, vs, aws, biass,
                                        wh1, gh, bh, mh, vh, awh1, biash,
                                        wh2, awh2);

    // #3: towers (frozen)
    towers_kernel<<<dim3(866, 2), 256, SMEM_TOWERS>>>(
        sin_, aws, biass, sbuf, kin, awk, biask, kbuf);

    // #4: xcorr v4 (ncu capture target)
    xcorr_kernel<<<BATCH * 16, 512, XC_SMEM>>>(sbuf, kbuf, feat);

    // #5: fused head (frozen)
    head_fused<<<1250, 256, HF_SMEM>>>(feat, awh1, biash, awh2, bh2, out);
}